// round 6
// baseline (speedup 1.0000x reference)
#include <cuda_runtime.h>
#include <stdint.h>
#include <math.h>
#include <algorithm>

// ---------------------------------------------------------------------------
// Permutation jax.random.permutation(key(42), 1024)[:256] — computed on HOST
// (threefry2x32 partitionable + one stable ascending sort round), uploaded as
// an async H2D memcpy to a device symbol (graph-capturable, no allocs).
// g_inv[col] = sample slot (0..255) or -1.
// ---------------------------------------------------------------------------

__device__ int g_inv[1024];

static uint32_t h_rotl32(uint32_t x, int r) { return (x << r) | (x >> (32 - r)); }

static void h_threefry2x32(uint32_t k0, uint32_t k1, uint32_t c0, uint32_t c1,
                           uint32_t& o0, uint32_t& o1) {
    uint32_t ks2 = k0 ^ k1 ^ 0x1BD11BDAu;
    uint32_t x0 = c0 + k0;
    uint32_t x1 = c1 + k1;
#define TF_G(r0, r1, r2, r3)                          \
    x0 += x1; x1 = h_rotl32(x1, r0); x1 ^= x0;        \
    x0 += x1; x1 = h_rotl32(x1, r1); x1 ^= x0;        \
    x0 += x1; x1 = h_rotl32(x1, r2); x1 ^= x0;        \
    x0 += x1; x1 = h_rotl32(x1, r3); x1 ^= x0;
    TF_G(13, 15, 26, 6)   x0 += k1;  x1 += ks2 + 1u;
    TF_G(17, 29, 16, 24)  x0 += ks2; x1 += k0 + 2u;
    TF_G(13, 15, 26, 6)   x0 += k0;  x1 += k1 + 3u;
    TF_G(17, 29, 16, 24)  x0 += k1;  x1 += ks2 + 4u;
    TF_G(13, 15, 26, 6)   x0 += ks2; x1 += k0 + 5u;
#undef TF_G
    o0 = x0; o1 = x1;
}

static int h_inv[1024];

static void build_perm_host() {
    uint32_t sk0, sk1;
    h_threefry2x32(0u, 42u, 0u, 1u, sk0, sk1);
    static uint64_t keys[1024];
    for (uint32_t i = 0; i < 1024; i++) {
        uint32_t b0, b1;
        h_threefry2x32(sk0, sk1, 0u, i, b0, b1);
        uint32_t bits = b0 ^ b1;
        keys[i] = ((uint64_t)bits << 32) | (uint64_t)i;
    }
    std::sort(keys, keys + 1024);
    for (int i = 0; i < 1024; i++) h_inv[i] = -1;
    for (int p = 0; p < 256; p++) {
        int col = (int)(keys[p] & 0xFFFFFFFFull);
        h_inv[col] = p;
    }
}

// ---------------------------------------------------------------------------
// Packed fp32x2 helpers (sm_100+): 2 fp32 lanes per instruction, fma pipe.
// ---------------------------------------------------------------------------

union F2U { float2 f; unsigned long long u; };

__device__ __forceinline__ float2 f2add(float2 a, float2 b) {
    F2U A, B, D; A.f = a; B.f = b;
    asm("add.rn.f32x2 %0, %1, %2;" : "=l"(D.u) : "l"(A.u), "l"(B.u));
    return D.f;
}
__device__ __forceinline__ float2 f2mul(float2 a, float2 b) {
    F2U A, B, D; A.f = a; B.f = b;
    asm("mul.rn.f32x2 %0, %1, %2;" : "=l"(D.u) : "l"(A.u), "l"(B.u));
    return D.f;
}
__device__ __forceinline__ float2 f2fma(float2 a, float2 b, float2 c) {
    F2U A, B, C, D; A.f = a; B.f = b; C.f = c;
    asm("fma.rn.f32x2 %0, %1, %2, %3;" : "=l"(D.u) : "l"(A.u), "l"(B.u), "l"(C.u));
    return D.f;
}

// ---------------------------------------------------------------------------
// Main LRF kernel: one block of 64 threads per batch row. 16 cols/thread,
// processed as 8 f32x2 pairs. 2 warps -> 4x fewer shuffle wavefronts than R4.
// Deflated fp32 eigen solve in warp 0 only.
// ---------------------------------------------------------------------------

__global__ void __launch_bounds__(64, 10) lrf_kernel(
    const float* __restrict__ x0,
    const float* __restrict__ x0i,
    float* __restrict__ out)
{
    const int b = blockIdx.x;
    const int t = threadIdx.x;
    const int w = t >> 5;
    const int lane = t & 31;

    __shared__ float redf[2][9];
    __shared__ float redv[2][3];
    __shared__ float sbc[3];
    __shared__ __align__(16) float samp0[256];   // 16B alignment: phase-4 float4 LDS
    __shared__ __align__(16) float samp1[256];
    __shared__ __align__(16) float samp2[256];

    const float px = __ldg(&x0[3 * b + 0]);
    const float py = __ldg(&x0[3 * b + 1]);
    const float pz = __ldg(&x0[3 * b + 2]);
    const float2 npx = make_float2(-px, -px);
    const float2 npy = make_float2(-py, -py);
    const float2 npz = make_float2(-pz, -pz);

    const float* base = x0i + (size_t)b * 3072;
    const int c0 = t * 16;

    float2 X2[8], Y2[8], Z2[8];
#pragma unroll
    for (int j = 0; j < 4; j++) {
        float4 a = *reinterpret_cast<const float4*>(base + c0 + 4 * j);
        float4 c = *reinterpret_cast<const float4*>(base + 1024 + c0 + 4 * j);
        float4 d = *reinterpret_cast<const float4*>(base + 2048 + c0 + 4 * j);
        X2[2 * j]     = f2add(make_float2(a.x, a.y), npx);
        X2[2 * j + 1] = f2add(make_float2(a.z, a.w), npx);
        Y2[2 * j]     = f2add(make_float2(c.x, c.y), npy);
        Y2[2 * j + 1] = f2add(make_float2(c.z, c.w), npy);
        Z2[2 * j]     = f2add(make_float2(d.x, d.y), npz);
        Z2[2 * j + 1] = f2add(make_float2(d.z, d.w), npz);
    }

    // scatter sampled deltas into smem slots
    int iv[16];
#pragma unroll
    for (int j = 0; j < 4; j++) {
        int4 q = *reinterpret_cast<const int4*>(&g_inv[c0 + 4 * j]);
        iv[4 * j] = q.x; iv[4 * j + 1] = q.y; iv[4 * j + 2] = q.z; iv[4 * j + 3] = q.w;
    }
#pragma unroll
    for (int k = 0; k < 16; k++) {
        int s = iv[k];
        if (s >= 0) {
            int j = k >> 1;
            if (k & 1) { samp0[s] = X2[j].y; samp1[s] = Y2[j].y; samp2[s] = Z2[j].y; }
            else       { samp0[s] = X2[j].x; samp1[s] = Y2[j].x; samp2[s] = Z2[j].x; }
        }
    }

    // ----- phase 1: covariance (6) + column sum (3), packed -----
    float2 a00 = {0.f, 0.f}, a01 = a00, a02 = a00, a11 = a00, a12 = a00, a22 = a00;
    float2 s0p = a00, s1p = a00, s2p = a00;
#pragma unroll
    for (int j = 0; j < 8; j++) {
        float2 x = X2[j], y = Y2[j], z = Z2[j];
        a00 = f2fma(x, x, a00); a01 = f2fma(x, y, a01); a02 = f2fma(x, z, a02);
        a11 = f2fma(y, y, a11); a12 = f2fma(y, z, a12); a22 = f2fma(z, z, a22);
        s0p = f2add(s0p, x); s1p = f2add(s1p, y); s2p = f2add(s2p, z);
    }
    float r0 = a00.x + a00.y, r1 = a01.x + a01.y, r2 = a02.x + a02.y;
    float r3 = a11.x + a11.y, r4 = a12.x + a12.y, r5 = a22.x + a22.y;
    float r6 = s0p.x + s0p.y, r7 = s1p.x + s1p.y, r8 = s2p.x + s2p.y;
#pragma unroll
    for (int o = 16; o; o >>= 1) {
        r0 += __shfl_down_sync(0xffffffffu, r0, o);
        r1 += __shfl_down_sync(0xffffffffu, r1, o);
        r2 += __shfl_down_sync(0xffffffffu, r2, o);
        r3 += __shfl_down_sync(0xffffffffu, r3, o);
        r4 += __shfl_down_sync(0xffffffffu, r4, o);
        r5 += __shfl_down_sync(0xffffffffu, r5, o);
        r6 += __shfl_down_sync(0xffffffffu, r6, o);
        r7 += __shfl_down_sync(0xffffffffu, r7, o);
        r8 += __shfl_down_sync(0xffffffffu, r8, o);
    }
    if (lane == 0) {
        redf[w][0] = r0; redf[w][1] = r1; redf[w][2] = r2;
        redf[w][3] = r3; redf[w][4] = r4; redf[w][5] = r5;
        redf[w][6] = r6; redf[w][7] = r7; redf[w][8] = r8;
    }
    __syncthreads();   // B1

    // ----- phase 2: eigen solve in warp 0 only (deflation, fp32) -----
    if (w == 0) {
        float sj = 0.f;
        if (lane < 9) sj = redf[0][lane] + redf[1][lane];
        const float invC = 1.0f / 1024.0f;
        const float M00 = __shfl_sync(0xffffffffu, sj, 0) * invC;
        const float M01 = __shfl_sync(0xffffffffu, sj, 1) * invC;
        const float M02 = __shfl_sync(0xffffffffu, sj, 2) * invC;
        const float M11 = __shfl_sync(0xffffffffu, sj, 3) * invC;
        const float M12 = __shfl_sync(0xffffffffu, sj, 4) * invC;
        const float M22 = __shfl_sync(0xffffffffu, sj, 5) * invC;
        const float S0  = __shfl_sync(0xffffffffu, sj, 6);
        const float S1  = __shfl_sync(0xffffffffu, sj, 7);
        const float S2  = __shfl_sync(0xffffffffu, sj, 8);

        // (a) largest eigenvalue via trig formula (well-conditioned at r->1)
        float q = (M00 + M11 + M22) * (1.0f / 3.0f);
        float d00 = M00 - q, d11 = M11 - q, d22 = M22 - q;
        float p2 = d00 * d00 + d11 * d11 + d22 * d22
                 + 2.0f * (M01 * M01 + M02 * M02 + M12 * M12);
        float p = sqrtf(p2 * (1.0f / 6.0f));
        float zx, zy, zz;
        if (p < 1e-18f) {
            zx = 0.f; zy = 0.f; zz = 1.f;
        } else {
            float ip = 1.0f / p;
            float c00 = d00 * ip, c11 = d11 * ip, c22 = d22 * ip;
            float c01 = M01 * ip, c02 = M02 * ip, c12 = M12 * ip;
            float det = c00 * (c11 * c22 - c12 * c12)
                      - c01 * (c01 * c22 - c12 * c02)
                      + c02 * (c01 * c12 - c11 * c02);
            float r = fminf(1.0f, fmaxf(-1.0f, 0.5f * det));
            float phi = acosf(r) * (1.0f / 3.0f);
            float lmax = q + 2.0f * p * cosf(phi);

            // (b) eigenvector e1 of lmax via row cross-products
            float m00 = M00 - lmax, m11 = M11 - lmax, m22 = M22 - lmax;
            float cx0 = M01 * M12 - M02 * m11;
            float cy0 = M02 * M01 - m00 * M12;
            float cz0 = m00 * m11 - M01 * M01;
            float cx1 = M01 * m22 - M02 * M12;
            float cy1 = M02 * M02 - m00 * m22;
            float cz1 = m00 * M12 - M01 * M02;
            float cx2 = m11 * m22 - M12 * M12;
            float cy2 = M12 * M02 - M01 * m22;
            float cz2 = M01 * M12 - m11 * M02;
            float n0 = cx0 * cx0 + cy0 * cy0 + cz0 * cz0;
            float n1 = cx1 * cx1 + cy1 * cy1 + cz1 * cz1;
            float n2 = cx2 * cx2 + cy2 * cy2 + cz2 * cz2;
            float ex, ey, ez, nn;
            if (n0 >= n1 && n0 >= n2)      { ex = cx0; ey = cy0; ez = cz0; nn = n0; }
            else if (n1 >= n2)             { ex = cx1; ey = cy1; ez = cz1; nn = n1; }
            else                           { ex = cx2; ey = cy2; ez = cz2; nn = n2; }
            if (nn < 1e-30f) { ex = 1.f; ey = 0.f; ez = 0.f; nn = 1.f; }
            float einv = rsqrtf(nn);
            ex *= einv; ey *= einv; ez *= einv;

            // (c) orthonormal basis {u,v} of complement of e1
            float uxx, uxy, uxz;
            float aex = fabsf(ex), aey = fabsf(ey), aez = fabsf(ez);
            if (aex <= aey && aex <= aez)      { uxx = 0.f; uxy = -ez; uxz =  ey; }
            else if (aey <= aez)               { uxx =  ez; uxy = 0.f; uxz = -ex; }
            else                               { uxx = -ey; uxy =  ex; uxz = 0.f; }
            float uinv = rsqrtf(uxx * uxx + uxy * uxy + uxz * uxz);
            uxx *= uinv; uxy *= uinv; uxz *= uinv;
            float vxx = ey * uxz - ez * uxy;
            float vxy = ez * uxx - ex * uxz;
            float vxz = ex * uxy - ey * uxx;

            // (d) 2x2 projected matrix B
            float Mux = fmaf(M00, uxx, fmaf(M01, uxy, M02 * uxz));
            float Muy = fmaf(M01, uxx, fmaf(M11, uxy, M12 * uxz));
            float Muz = fmaf(M02, uxx, fmaf(M12, uxy, M22 * uxz));
            float Mvx = fmaf(M00, vxx, fmaf(M01, vxy, M02 * vxz));
            float Mvy = fmaf(M01, vxx, fmaf(M11, vxy, M12 * vxz));
            float Mvz = fmaf(M02, vxx, fmaf(M12, vxy, M22 * vxz));
            float b00 = fmaf(uxx, Mux, fmaf(uxy, Muy, uxz * Muz));
            float b01 = fmaf(uxx, Mvx, fmaf(uxy, Mvy, uxz * Mvz));
            float b11 = fmaf(vxx, Mvx, fmaf(vxy, Mvy, vxz * Mvz));

            // (e) smallest eigenvector of B (cancellation-free)
            float half = 0.5f * (b00 - b11);
            float rt = sqrtf(fmaf(half, half, b01 * b01));
            float cc, ss;
            if (half >= 0.f) { cc = b01;       ss = -(half + rt); }
            else             { cc = rt - half; ss = -b01; }
            float cn2 = fmaf(cc, cc, ss * ss);
            if (cn2 < 1e-30f) { cc = 1.f; ss = 0.f; cn2 = 1.f; }
            float cninv = rsqrtf(cn2);
            cc *= cninv; ss *= cninv;

            zx = fmaf(cc, uxx, ss * vxx);
            zy = fmaf(cc, uxy, ss * vxy);
            zz = fmaf(cc, uxz, ss * vxz);
        }

        float sgn = (-(zx * S0 + zy * S1 + zz * S2) < 0.f) ? -1.f : 1.f;
        if (lane == 0) {
            sbc[0] = zx * sgn;
            sbc[1] = zy * sgn;
            sbc[2] = zz * sgn;
        }
    }
    __syncthreads();   // B2

    const float zpx = sbc[0], zpy = sbc[1], zpz = sbc[2];
    const float2 zx2 = make_float2(zpx, zpx);
    const float2 zy2 = make_float2(zpy, zpy);
    const float2 zz2 = make_float2(zpz, zpz);
    const float2 neg1 = make_float2(-1.f, -1.f);

    // ----- phase 3: vi_c accumulation, packed -----
    float2 v0p = {0.f, 0.f}, v1p = v0p, v2p = v0p;
#pragma unroll
    for (int j = 0; j < 8; j++) {
        float2 x = X2[j], y = Y2[j], z = Z2[j];
        float2 nrm = f2fma(zx2, x, f2fma(zy2, y, f2mul(zz2, z)));
        float2 d2  = f2fma(x, x, f2fma(y, y, f2mul(z, z)));
        float2 am  = make_float2(1.0f - sqrtf(d2.x), 1.0f - sqrtf(d2.y));
        float2 coef = f2mul(f2mul(am, am), f2mul(nrm, nrm));
        float2 nn = f2mul(nrm, neg1);
        v0p = f2fma(coef, f2fma(nn, zx2, x), v0p);
        v1p = f2fma(coef, f2fma(nn, zy2, y), v1p);
        v2p = f2fma(coef, f2fma(nn, zz2, z), v2p);
    }
    float v0 = v0p.x + v0p.y, v1 = v1p.x + v1p.y, v2 = v2p.x + v2p.y;
#pragma unroll
    for (int o = 16; o; o >>= 1) {
        v0 += __shfl_down_sync(0xffffffffu, v0, o);
        v1 += __shfl_down_sync(0xffffffffu, v1, o);
        v2 += __shfl_down_sync(0xffffffffu, v2, o);
    }
    if (lane == 0) {
        redv[w][0] = v0; redv[w][1] = v1; redv[w][2] = v2;
    }
    __syncthreads();   // B3

    float c0f = redv[0][0] + redv[1][0];
    float c1f = redv[0][1] + redv[1][1];
    float c2f = redv[0][2] + redv[1][2];
    float nrm2 = fmaf(c0f, c0f, fmaf(c1f, c1f, c2f * c2f));
    float invn = rsqrtf(nrm2);
    float ax = c0f * invn, ay = c1f * invn, az = c2f * invn;
    float yx = ay * zpz - az * zpy;
    float yy = az * zpx - ax * zpz;
    float yz = ax * zpy - ay * zpx;

    // ----- phase 4: project 4 sampled columns per thread (float4 LDS/STG) -----
    const int s0i = 4 * t;
    float4 vx4 = *reinterpret_cast<const float4*>(&samp0[s0i]);
    float4 vy4 = *reinterpret_cast<const float4*>(&samp1[s0i]);
    float4 vz4 = *reinterpret_cast<const float4*>(&samp2[s0i]);
    float2 xa = make_float2(vx4.x, vx4.y), xb = make_float2(vx4.z, vx4.w);
    float2 ya = make_float2(vy4.x, vy4.y), yb = make_float2(vy4.z, vy4.w);
    float2 za = make_float2(vz4.x, vz4.y), zb = make_float2(vz4.z, vz4.w);

    float2 ax2 = make_float2(ax, ax), ay2 = make_float2(ay, ay), az2 = make_float2(az, az);
    float2 yx2 = make_float2(yx, yx), yy2 = make_float2(yy, yy), yz2 = make_float2(yz, yz);

    float2 oa0 = f2fma(ax2, xa, f2fma(ay2, ya, f2mul(az2, za)));
    float2 ob0 = f2fma(ax2, xb, f2fma(ay2, yb, f2mul(az2, zb)));
    float2 oa1 = f2fma(yx2, xa, f2fma(yy2, ya, f2mul(yz2, za)));
    float2 ob1 = f2fma(yx2, xb, f2fma(yy2, yb, f2mul(yz2, zb)));
    float2 oa2 = f2fma(zx2, xa, f2fma(zy2, ya, f2mul(zz2, za)));
    float2 ob2 = f2fma(zx2, xb, f2fma(zy2, yb, f2mul(zz2, zb)));

    float* ob = out + (size_t)b * 768 + s0i;
    *reinterpret_cast<float4*>(ob)       = make_float4(oa0.x, oa0.y, ob0.x, ob0.y);
    *reinterpret_cast<float4*>(ob + 256) = make_float4(oa1.x, oa1.y, ob1.x, ob1.y);
    *reinterpret_cast<float4*>(ob + 512) = make_float4(oa2.x, oa2.y, ob2.x, ob2.y);
}

// ---------------------------------------------------------------------------

extern "C" void kernel_launch(void* const* d_in, const int* in_sizes, int n_in,
                              void* d_out, int out_size) {
    const float* x0  = (const float*)d_in[0];
    const float* x0i = (const float*)d_in[1];
    if (n_in >= 2 && in_sizes[0] > in_sizes[1]) {
        const float* tmp = x0; x0 = x0i; x0i = tmp;
    }
    int B;
    if (in_sizes[0] <= in_sizes[1]) B = in_sizes[0] / 3;
    else                            B = in_sizes[1] / 3;

    float* out = (float*)d_out;

    build_perm_host();  // deterministic; recomputed every call (stateless)
    cudaMemcpyToSymbolAsync(g_inv, h_inv, sizeof(h_inv), 0,
                            cudaMemcpyHostToDevice, 0);

    lrf_kernel<<<B, 64>>>(x0, x0i, out);
}

// round 7
// speedup vs baseline: 1.1743x; 1.1743x over previous
#include <cuda_runtime.h>
#include <stdint.h>
#include <math.h>
#include <algorithm>

// ---------------------------------------------------------------------------
// Permutation jax.random.permutation(key(42), 1024)[:256] — computed on HOST
// (threefry2x32 partitionable + one stable ascending sort round), uploaded as
// an async H2D memcpy to a device symbol (graph-capturable, no allocs).
// g_inv[col] = sample slot (0..255) or -1.
// ---------------------------------------------------------------------------

__device__ int g_inv[1024];

static uint32_t h_rotl32(uint32_t x, int r) { return (x << r) | (x >> (32 - r)); }

static void h_threefry2x32(uint32_t k0, uint32_t k1, uint32_t c0, uint32_t c1,
                           uint32_t& o0, uint32_t& o1) {
    uint32_t ks2 = k0 ^ k1 ^ 0x1BD11BDAu;
    uint32_t x0 = c0 + k0;
    uint32_t x1 = c1 + k1;
#define TF_G(r0, r1, r2, r3)                          \
    x0 += x1; x1 = h_rotl32(x1, r0); x1 ^= x0;        \
    x0 += x1; x1 = h_rotl32(x1, r1); x1 ^= x0;        \
    x0 += x1; x1 = h_rotl32(x1, r2); x1 ^= x0;        \
    x0 += x1; x1 = h_rotl32(x1, r3); x1 ^= x0;
    TF_G(13, 15, 26, 6)   x0 += k1;  x1 += ks2 + 1u;
    TF_G(17, 29, 16, 24)  x0 += ks2; x1 += k0 + 2u;
    TF_G(13, 15, 26, 6)   x0 += k0;  x1 += k1 + 3u;
    TF_G(17, 29, 16, 24)  x0 += k1;  x1 += ks2 + 4u;
    TF_G(13, 15, 26, 6)   x0 += ks2; x1 += k0 + 5u;
#undef TF_G
    o0 = x0; o1 = x1;
}

static int h_inv[1024];

static void build_perm_host() {
    uint32_t sk0, sk1;
    h_threefry2x32(0u, 42u, 0u, 1u, sk0, sk1);
    static uint64_t keys[1024];
    for (uint32_t i = 0; i < 1024; i++) {
        uint32_t b0, b1;
        h_threefry2x32(sk0, sk1, 0u, i, b0, b1);
        uint32_t bits = b0 ^ b1;
        keys[i] = ((uint64_t)bits << 32) | (uint64_t)i;
    }
    std::sort(keys, keys + 1024);
    for (int i = 0; i < 1024; i++) h_inv[i] = -1;
    for (int p = 0; p < 256; p++) {
        int col = (int)(keys[p] & 0xFFFFFFFFull);
        h_inv[col] = p;
    }
}

// ---------------------------------------------------------------------------
// Packed fp32x2 helpers (sm_100+): 2 fp32 lanes per instruction, fma pipe.
// ---------------------------------------------------------------------------

union F2U { float2 f; unsigned long long u; };

__device__ __forceinline__ float2 f2add(float2 a, float2 b) {
    F2U A, B, D; A.f = a; B.f = b;
    asm("add.rn.f32x2 %0, %1, %2;" : "=l"(D.u) : "l"(A.u), "l"(B.u));
    return D.f;
}
__device__ __forceinline__ float2 f2mul(float2 a, float2 b) {
    F2U A, B, D; A.f = a; B.f = b;
    asm("mul.rn.f32x2 %0, %1, %2;" : "=l"(D.u) : "l"(A.u), "l"(B.u));
    return D.f;
}
__device__ __forceinline__ float2 f2fma(float2 a, float2 b, float2 c) {
    F2U A, B, C, D; A.f = a; B.f = b; C.f = c;
    asm("fma.rn.f32x2 %0, %1, %2, %3;" : "=l"(D.u) : "l"(A.u), "l"(B.u), "l"(C.u));
    return D.f;
}

// ---------------------------------------------------------------------------
// Main LRF kernel: one block of 128 threads per batch row (R4's winning shape).
// 8 cols/thread as 4 f32x2 pairs -> low register pressure + packed math.
// Phase-1 reduction: 3 shuffle levels to 4 lanes, cross-warp combine in warp 0.
// ---------------------------------------------------------------------------

__global__ void __launch_bounds__(128, 8) lrf_kernel(
    const float* __restrict__ x0,
    const float* __restrict__ x0i,
    float* __restrict__ out)
{
    const int b = blockIdx.x;
    const int t = threadIdx.x;
    const int w = t >> 5;
    const int lane = t & 31;

    __shared__ float redf[16][9];   // [warp*4 + lane(<4)][component]
    __shared__ float redv[4][3];
    __shared__ float sbc[3];
    __shared__ __align__(16) float samp0[256];
    __shared__ __align__(16) float samp1[256];
    __shared__ __align__(16) float samp2[256];

    const float px = __ldg(&x0[3 * b + 0]);
    const float py = __ldg(&x0[3 * b + 1]);
    const float pz = __ldg(&x0[3 * b + 2]);
    const float2 npx = make_float2(-px, -px);
    const float2 npy = make_float2(-py, -py);
    const float2 npz = make_float2(-pz, -pz);

    const float* base = x0i + (size_t)b * 3072;
    const int c0 = t * 8;

    float4 xa = *reinterpret_cast<const float4*>(base + c0);
    float4 xb = *reinterpret_cast<const float4*>(base + c0 + 4);
    float4 ya = *reinterpret_cast<const float4*>(base + 1024 + c0);
    float4 yb = *reinterpret_cast<const float4*>(base + 1024 + c0 + 4);
    float4 za = *reinterpret_cast<const float4*>(base + 2048 + c0);
    float4 zb = *reinterpret_cast<const float4*>(base + 2048 + c0 + 4);
    int4 iva = *reinterpret_cast<const int4*>(&g_inv[c0]);
    int4 ivb = *reinterpret_cast<const int4*>(&g_inv[c0 + 4]);

    float2 X2[4] = { f2add(make_float2(xa.x, xa.y), npx),
                     f2add(make_float2(xa.z, xa.w), npx),
                     f2add(make_float2(xb.x, xb.y), npx),
                     f2add(make_float2(xb.z, xb.w), npx) };
    float2 Y2[4] = { f2add(make_float2(ya.x, ya.y), npy),
                     f2add(make_float2(ya.z, ya.w), npy),
                     f2add(make_float2(yb.x, yb.y), npy),
                     f2add(make_float2(yb.z, yb.w), npy) };
    float2 Z2[4] = { f2add(make_float2(za.x, za.y), npz),
                     f2add(make_float2(za.z, za.w), npz),
                     f2add(make_float2(zb.x, zb.y), npz),
                     f2add(make_float2(zb.z, zb.w), npz) };
    int iv[8] = {iva.x, iva.y, iva.z, iva.w, ivb.x, ivb.y, ivb.z, ivb.w};

    // scatter sampled deltas into smem slots
#pragma unroll
    for (int k = 0; k < 8; k++) {
        int s = iv[k];
        if (s >= 0) {
            int j = k >> 1;
            if (k & 1) { samp0[s] = X2[j].y; samp1[s] = Y2[j].y; samp2[s] = Z2[j].y; }
            else       { samp0[s] = X2[j].x; samp1[s] = Y2[j].x; samp2[s] = Z2[j].x; }
        }
    }

    // ----- phase 1: covariance (6) + column sum (3), packed -----
    float2 a00 = {0.f, 0.f}, a01 = a00, a02 = a00, a11 = a00, a12 = a00, a22 = a00;
    float2 s0p = a00, s1p = a00, s2p = a00;
#pragma unroll
    for (int j = 0; j < 4; j++) {
        float2 x = X2[j], y = Y2[j], z = Z2[j];
        a00 = f2fma(x, x, a00); a01 = f2fma(x, y, a01); a02 = f2fma(x, z, a02);
        a11 = f2fma(y, y, a11); a12 = f2fma(y, z, a12); a22 = f2fma(z, z, a22);
        s0p = f2add(s0p, x); s1p = f2add(s1p, y); s2p = f2add(s2p, z);
    }
    float r0 = a00.x + a00.y, r1 = a01.x + a01.y, r2 = a02.x + a02.y;
    float r3 = a11.x + a11.y, r4 = a12.x + a12.y, r5 = a22.x + a22.y;
    float r6 = s0p.x + s0p.y, r7 = s1p.x + s1p.y, r8 = s2p.x + s2p.y;
    // 3-level tree: stop at 4 lanes (saves 2 levels x 9 shuffles per warp)
#pragma unroll
    for (int o = 16; o >= 4; o >>= 1) {
        r0 += __shfl_down_sync(0xffffffffu, r0, o);
        r1 += __shfl_down_sync(0xffffffffu, r1, o);
        r2 += __shfl_down_sync(0xffffffffu, r2, o);
        r3 += __shfl_down_sync(0xffffffffu, r3, o);
        r4 += __shfl_down_sync(0xffffffffu, r4, o);
        r5 += __shfl_down_sync(0xffffffffu, r5, o);
        r6 += __shfl_down_sync(0xffffffffu, r6, o);
        r7 += __shfl_down_sync(0xffffffffu, r7, o);
        r8 += __shfl_down_sync(0xffffffffu, r8, o);
    }
    if (lane < 4) {
        const int row = w * 4 + lane;
        redf[row][0] = r0; redf[row][1] = r1; redf[row][2] = r2;
        redf[row][3] = r3; redf[row][4] = r4; redf[row][5] = r5;
        redf[row][6] = r6; redf[row][7] = r7; redf[row][8] = r8;
    }
    __syncthreads();   // B1

    // ----- phase 2: eigen solve in warp 0 only (deflation, fp32) -----
    if (w == 0) {
        float sj = 0.f;
        if (lane < 9) {
#pragma unroll
            for (int i = 0; i < 16; i++) sj += redf[i][lane];
        }
        const float invC = 1.0f / 1024.0f;
        const float M00 = __shfl_sync(0xffffffffu, sj, 0) * invC;
        const float M01 = __shfl_sync(0xffffffffu, sj, 1) * invC;
        const float M02 = __shfl_sync(0xffffffffu, sj, 2) * invC;
        const float M11 = __shfl_sync(0xffffffffu, sj, 3) * invC;
        const float M12 = __shfl_sync(0xffffffffu, sj, 4) * invC;
        const float M22 = __shfl_sync(0xffffffffu, sj, 5) * invC;
        const float S0  = __shfl_sync(0xffffffffu, sj, 6);
        const float S1  = __shfl_sync(0xffffffffu, sj, 7);
        const float S2  = __shfl_sync(0xffffffffu, sj, 8);

        // (a) largest eigenvalue via trig formula (well-conditioned at r->1)
        float q = (M00 + M11 + M22) * (1.0f / 3.0f);
        float d00 = M00 - q, d11 = M11 - q, d22 = M22 - q;
        float p2 = d00 * d00 + d11 * d11 + d22 * d22
                 + 2.0f * (M01 * M01 + M02 * M02 + M12 * M12);
        float p = sqrtf(p2 * (1.0f / 6.0f));
        float zx, zy, zz;
        if (p < 1e-18f) {
            zx = 0.f; zy = 0.f; zz = 1.f;
        } else {
            float ip = 1.0f / p;
            float c00 = d00 * ip, c11 = d11 * ip, c22 = d22 * ip;
            float c01 = M01 * ip, c02 = M02 * ip, c12 = M12 * ip;
            float det = c00 * (c11 * c22 - c12 * c12)
                      - c01 * (c01 * c22 - c12 * c02)
                      + c02 * (c01 * c12 - c11 * c02);
            float r = fminf(1.0f, fmaxf(-1.0f, 0.5f * det));
            float phi = acosf(r) * (1.0f / 3.0f);
            float lmax = q + 2.0f * p * cosf(phi);

            // (b) eigenvector e1 of lmax via row cross-products
            float m00 = M00 - lmax, m11 = M11 - lmax, m22 = M22 - lmax;
            float cx0 = M01 * M12 - M02 * m11;
            float cy0 = M02 * M01 - m00 * M12;
            float cz0 = m00 * m11 - M01 * M01;
            float cx1 = M01 * m22 - M02 * M12;
            float cy1 = M02 * M02 - m00 * m22;
            float cz1 = m00 * M12 - M01 * M02;
            float cx2 = m11 * m22 - M12 * M12;
            float cy2 = M12 * M02 - M01 * m22;
            float cz2 = M01 * M12 - m11 * M02;
            float n0 = cx0 * cx0 + cy0 * cy0 + cz0 * cz0;
            float n1 = cx1 * cx1 + cy1 * cy1 + cz1 * cz1;
            float n2 = cx2 * cx2 + cy2 * cy2 + cz2 * cz2;
            float ex, ey, ez, nn;
            if (n0 >= n1 && n0 >= n2)      { ex = cx0; ey = cy0; ez = cz0; nn = n0; }
            else if (n1 >= n2)             { ex = cx1; ey = cy1; ez = cz1; nn = n1; }
            else                           { ex = cx2; ey = cy2; ez = cz2; nn = n2; }
            if (nn < 1e-30f) { ex = 1.f; ey = 0.f; ez = 0.f; nn = 1.f; }
            float einv = rsqrtf(nn);
            ex *= einv; ey *= einv; ez *= einv;

            // (c) orthonormal basis {u,v} of complement of e1
            float uxx, uxy, uxz;
            float aex = fabsf(ex), aey = fabsf(ey), aez = fabsf(ez);
            if (aex <= aey && aex <= aez)      { uxx = 0.f; uxy = -ez; uxz =  ey; }
            else if (aey <= aez)               { uxx =  ez; uxy = 0.f; uxz = -ex; }
            else                               { uxx = -ey; uxy =  ex; uxz = 0.f; }
            float uinv = rsqrtf(uxx * uxx + uxy * uxy + uxz * uxz);
            uxx *= uinv; uxy *= uinv; uxz *= uinv;
            float vxx = ey * uxz - ez * uxy;
            float vxy = ez * uxx - ex * uxz;
            float vxz = ex * uxy - ey * uxx;

            // (d) 2x2 projected matrix B
            float Mux = fmaf(M00, uxx, fmaf(M01, uxy, M02 * uxz));
            float Muy = fmaf(M01, uxx, fmaf(M11, uxy, M12 * uxz));
            float Muz = fmaf(M02, uxx, fmaf(M12, uxy, M22 * uxz));
            float Mvx = fmaf(M00, vxx, fmaf(M01, vxy, M02 * vxz));
            float Mvy = fmaf(M01, vxx, fmaf(M11, vxy, M12 * vxz));
            float Mvz = fmaf(M02, vxx, fmaf(M12, vxy, M22 * vxz));
            float b00 = fmaf(uxx, Mux, fmaf(uxy, Muy, uxz * Muz));
            float b01 = fmaf(uxx, Mvx, fmaf(uxy, Mvy, uxz * Mvz));
            float b11 = fmaf(vxx, Mvx, fmaf(vxy, Mvy, vxz * Mvz));

            // (e) smallest eigenvector of B (cancellation-free)
            float half = 0.5f * (b00 - b11);
            float rt = sqrtf(fmaf(half, half, b01 * b01));
            float cc, ss;
            if (half >= 0.f) { cc = b01;       ss = -(half + rt); }
            else             { cc = rt - half; ss = -b01; }
            float cn2 = fmaf(cc, cc, ss * ss);
            if (cn2 < 1e-30f) { cc = 1.f; ss = 0.f; cn2 = 1.f; }
            float cninv = rsqrtf(cn2);
            cc *= cninv; ss *= cninv;

            zx = fmaf(cc, uxx, ss * vxx);
            zy = fmaf(cc, uxy, ss * vxy);
            zz = fmaf(cc, uxz, ss * vxz);
        }

        float sgn = (-(zx * S0 + zy * S1 + zz * S2) < 0.f) ? -1.f : 1.f;
        if (lane == 0) {
            sbc[0] = zx * sgn;
            sbc[1] = zy * sgn;
            sbc[2] = zz * sgn;
        }
    }
    __syncthreads();   // B2

    const float zpx = sbc[0], zpy = sbc[1], zpz = sbc[2];
    const float2 zx2 = make_float2(zpx, zpx);
    const float2 zy2 = make_float2(zpy, zpy);
    const float2 zz2 = make_float2(zpz, zpz);
    const float2 neg1 = make_float2(-1.f, -1.f);

    // ----- phase 3: vi_c accumulation, packed -----
    float2 v0p = {0.f, 0.f}, v1p = v0p, v2p = v0p;
#pragma unroll
    for (int j = 0; j < 4; j++) {
        float2 x = X2[j], y = Y2[j], z = Z2[j];
        float2 nrm = f2fma(zx2, x, f2fma(zy2, y, f2mul(zz2, z)));
        float2 d2  = f2fma(x, x, f2fma(y, y, f2mul(z, z)));
        float2 am  = make_float2(1.0f - sqrtf(d2.x), 1.0f - sqrtf(d2.y));
        float2 coef = f2mul(f2mul(am, am), f2mul(nrm, nrm));
        float2 nn = f2mul(nrm, neg1);
        v0p = f2fma(coef, f2fma(nn, zx2, x), v0p);
        v1p = f2fma(coef, f2fma(nn, zy2, y), v1p);
        v2p = f2fma(coef, f2fma(nn, zz2, z), v2p);
    }
    float v0 = v0p.x + v0p.y, v1 = v1p.x + v1p.y, v2 = v2p.x + v2p.y;
#pragma unroll
    for (int o = 16; o; o >>= 1) {
        v0 += __shfl_down_sync(0xffffffffu, v0, o);
        v1 += __shfl_down_sync(0xffffffffu, v1, o);
        v2 += __shfl_down_sync(0xffffffffu, v2, o);
    }
    if (lane == 0) {
        redv[w][0] = v0; redv[w][1] = v1; redv[w][2] = v2;
    }
    __syncthreads();   // B3

    float c0f = redv[0][0] + redv[1][0] + redv[2][0] + redv[3][0];
    float c1f = redv[0][1] + redv[1][1] + redv[2][1] + redv[3][1];
    float c2f = redv[0][2] + redv[1][2] + redv[2][2] + redv[3][2];
    float nrm2 = fmaf(c0f, c0f, fmaf(c1f, c1f, c2f * c2f));
    float invn = rsqrtf(nrm2);
    float ax = c0f * invn, ay = c1f * invn, az = c2f * invn;
    float yx = ay * zpz - az * zpy;
    float yy = az * zpx - ax * zpz;
    float yz = ax * zpy - ay * zpx;

    // ----- phase 4: project 2 sampled columns per thread (float2, packed) -----
    const int s0i = 2 * t;
    float2 vx2 = *reinterpret_cast<const float2*>(&samp0[s0i]);
    float2 vy2 = *reinterpret_cast<const float2*>(&samp1[s0i]);
    float2 vz2 = *reinterpret_cast<const float2*>(&samp2[s0i]);

    float2 ax2 = make_float2(ax, ax), ay2 = make_float2(ay, ay), az2 = make_float2(az, az);
    float2 yx2 = make_float2(yx, yx), yy2 = make_float2(yy, yy), yz2 = make_float2(yz, yz);

    float2 o0 = f2fma(ax2, vx2, f2fma(ay2, vy2, f2mul(az2, vz2)));
    float2 o1 = f2fma(yx2, vx2, f2fma(yy2, vy2, f2mul(yz2, vz2)));
    float2 o2 = f2fma(zx2, vx2, f2fma(zy2, vy2, f2mul(zz2, vz2)));

    float* ob = out + (size_t)b * 768 + s0i;
    *reinterpret_cast<float2*>(ob)       = o0;
    *reinterpret_cast<float2*>(ob + 256) = o1;
    *reinterpret_cast<float2*>(ob + 512) = o2;
}

// ---------------------------------------------------------------------------

extern "C" void kernel_launch(void* const* d_in, const int* in_sizes, int n_in,
                              void* d_out, int out_size) {
    const float* x0  = (const float*)d_in[0];
    const float* x0i = (const float*)d_in[1];
    if (n_in >= 2 && in_sizes[0] > in_sizes[1]) {
        const float* tmp = x0; x0 = x0i; x0i = tmp;
    }
    int B;
    if (in_sizes[0] <= in_sizes[1]) B = in_sizes[0] / 3;
    else                            B = in_sizes[1] / 3;

    float* out = (float*)d_out;

    build_perm_host();  // deterministic; recomputed every call (stateless)
    cudaMemcpyToSymbolAsync(g_inv, h_inv, sizeof(h_inv), 0,
                            cudaMemcpyHostToDevice, 0);

    lrf_kernel<<<B, 128>>>(x0, x0i, out);
}